// round 5
// baseline (speedup 1.0000x reference)
#include <cuda_runtime.h>
#include <cuda_bf16.h>
#include <cstdint>

#define HID  4096
#define TOK  8192
#define BM   128
#define BN   128
#define BK   64
#define SROW 80   // smem row stride (bytes): 80 = 20 banks -> conflict-free frag loads

// Scratch (static device globals: allocation-guard safe)
__device__ int8_t g_xq[(size_t)TOK * HID];            // 32 MB quantized activations
__device__ float  g_ascale[TOK];
__device__ int8_t g_w[(size_t)3 * HID * HID];         // 48 MB normalized int8 weights
__device__ int    g_dtype_flag;                       // 0=int8 1=int32 2=float32 3=bf16

// ---------------------------------------------------------------------------
// Kernel 0a: sniff the dtype the harness used for the int8 weight tensors.
// Reads 256 words (1 KB, safe: buffer >= 16 MB under any dtype) and votes.
// ---------------------------------------------------------------------------
__global__ void detect_dtype_kernel(const unsigned int* __restrict__ w)
{
    const int lane = threadIdx.x;
    int vi8 = 0, vi32 = 0, vf32 = 0, vbf = 0;
    #pragma unroll
    for (int i = 0; i < 8; i++) {
        unsigned int u = w[lane + i * 32];
        int s = (int)u;
        if (s >= -8 && s <= 7) vi32++;
        float f = __uint_as_float(u);
        if (f == rintf(f) && fabsf(f) <= 8.f) vf32++;
        bool ok8 = true;
        #pragma unroll
        for (int b = 0; b < 4; b++) {
            int by = (int)(signed char)(u >> (8 * b));
            if (by < -8 || by > 7) ok8 = false;
        }
        vi8 += ok8 ? 1 : 0;
        bool okb = true;
        #pragma unroll
        for (int h = 0; h < 2; h++) {
            __nv_bfloat16_raw r; r.x = (unsigned short)(u >> (16 * h));
            float fb = __bfloat162float(__nv_bfloat16(r));
            if (!(fb == rintf(fb) && fabsf(fb) <= 8.f)) okb = false;
        }
        vbf += okb ? 1 : 0;
    }
    vi8  = __reduce_add_sync(0xffffffffu, vi8);
    vi32 = __reduce_add_sync(0xffffffffu, vi32);
    vf32 = __reduce_add_sync(0xffffffffu, vf32);
    vbf  = __reduce_add_sync(0xffffffffu, vbf);
    if (lane == 0) {
        // Priority: int32 data also passes the int8 byte test (sign-ext bytes
        // 0x00/0xFF are valid int8), and float32 small-int data also passes
        // the bf16 test (upper half == bf16 encoding, lower half zero).
        int f;
        if      (vi32 >= 240) f = 1;
        else if (vi8  >= 240) f = 0;
        else if (vf32 >= 240) f = 2;
        else                  f = 3;
        g_dtype_flag = f;
    }
}

// ---------------------------------------------------------------------------
// Kernel 0b: normalize the three weight tensors into int8 scratch.
// grid = (HID*HID/4/256, 3); 4 elements per thread.
// ---------------------------------------------------------------------------
__global__ __launch_bounds__(256) void convert_weights_kernel(
    const void* __restrict__ w0, const void* __restrict__ w1, const void* __restrict__ w2)
{
    const void* src = (blockIdx.y == 0) ? w0 : (blockIdx.y == 1 ? w1 : w2);
    int8_t* dst = g_w + (size_t)blockIdx.y * HID * HID;
    const size_t i = (size_t)blockIdx.x * blockDim.x + threadIdx.x;   // 4-elem group
    const int flag = g_dtype_flag;

    char4 v;
    if (flag == 0) {
        v = ((const char4*)src)[i];
    } else if (flag == 1) {
        int4 t = ((const int4*)src)[i];
        v.x = (signed char)t.x; v.y = (signed char)t.y;
        v.z = (signed char)t.z; v.w = (signed char)t.w;
    } else if (flag == 2) {
        float4 t = ((const float4*)src)[i];
        v.x = (signed char)__float2int_rn(t.x);
        v.y = (signed char)__float2int_rn(t.y);
        v.z = (signed char)__float2int_rn(t.z);
        v.w = (signed char)__float2int_rn(t.w);
    } else {
        const __nv_bfloat162* p = (const __nv_bfloat162*)src;
        __nv_bfloat162 a = p[i * 2], b = p[i * 2 + 1];
        v.x = (signed char)__float2int_rn(__bfloat162float(a.x));
        v.y = (signed char)__float2int_rn(__bfloat162float(a.y));
        v.z = (signed char)__float2int_rn(__bfloat162float(b.x));
        v.w = (signed char)__float2int_rn(__bfloat162float(b.y));
    }
    ((char4*)dst)[i] = v;
}

// ---------------------------------------------------------------------------
// Kernel 1: per-token 64x64 transform (fp32) + amax + int4-range quantize
//   xt[m][n] = sum_{l,r} LT[m][l] * X[l][r] * RT[r][n]
// ---------------------------------------------------------------------------
__global__ __launch_bounds__(256) void transform_quant_kernel(
    const float* __restrict__ hs,
    const float* __restrict__ lt,   // [m][l]
    const float* __restrict__ rt)   // [r][n]
{
    __shared__ float sX[4096];      // X, then reused as Tmp = X @ RT
    __shared__ float sRT[4096];     // head also reused as reduction scratch
    __shared__ float sLT[4096];

    const int tid   = threadIdx.x;
    const long token = blockIdx.x;
    const float* x = hs + token * (long)HID;

    #pragma unroll
    for (int i = 0; i < 4; i++) {
        int idx = tid + i * 256;
        ((float4*)sX)[idx]  = ((const float4*)x)[idx];
        ((float4*)sRT)[idx] = ((const float4*)rt)[idx];
        ((float4*)sLT)[idx] = ((const float4*)lt)[idx];
    }
    __syncthreads();

    const int ty = tid >> 4;
    const int tx = tid & 15;
    const int r0 = ty * 4;
    const int c0 = tx * 4;

    float acc[4][4];

    // -------- Tmp[l][n] = sum_r X[l][r] * RT[r][n] --------
    #pragma unroll
    for (int i = 0; i < 4; i++)
        #pragma unroll
        for (int j = 0; j < 4; j++) acc[i][j] = 0.f;

    #pragma unroll 8
    for (int r = 0; r < 64; r++) {
        float4 b = *(const float4*)&sRT[r * 64 + c0];
        float a0 = sX[(r0 + 0) * 64 + r];
        float a1 = sX[(r0 + 1) * 64 + r];
        float a2 = sX[(r0 + 2) * 64 + r];
        float a3 = sX[(r0 + 3) * 64 + r];
        acc[0][0] += a0 * b.x; acc[0][1] += a0 * b.y; acc[0][2] += a0 * b.z; acc[0][3] += a0 * b.w;
        acc[1][0] += a1 * b.x; acc[1][1] += a1 * b.y; acc[1][2] += a1 * b.z; acc[1][3] += a1 * b.w;
        acc[2][0] += a2 * b.x; acc[2][1] += a2 * b.y; acc[2][2] += a2 * b.z; acc[2][3] += a2 * b.w;
        acc[3][0] += a3 * b.x; acc[3][1] += a3 * b.y; acc[3][2] += a3 * b.z; acc[3][3] += a3 * b.w;
    }
    __syncthreads();

    #pragma unroll
    for (int i = 0; i < 4; i++)
        *(float4*)&sX[(r0 + i) * 64 + c0] =
            make_float4(acc[i][0], acc[i][1], acc[i][2], acc[i][3]);
    __syncthreads();

    // -------- xt[m][n] = sum_l LT[m][l] * Tmp[l][n] --------
    #pragma unroll
    for (int i = 0; i < 4; i++)
        #pragma unroll
        for (int j = 0; j < 4; j++) acc[i][j] = 0.f;

    #pragma unroll 8
    for (int l = 0; l < 64; l++) {
        float4 b = *(const float4*)&sX[l * 64 + c0];
        float a0 = sLT[(r0 + 0) * 64 + l];
        float a1 = sLT[(r0 + 1) * 64 + l];
        float a2 = sLT[(r0 + 2) * 64 + l];
        float a3 = sLT[(r0 + 3) * 64 + l];
        acc[0][0] += a0 * b.x; acc[0][1] += a0 * b.y; acc[0][2] += a0 * b.z; acc[0][3] += a0 * b.w;
        acc[1][0] += a1 * b.x; acc[1][1] += a1 * b.y; acc[1][2] += a1 * b.z; acc[1][3] += a1 * b.w;
        acc[2][0] += a2 * b.x; acc[2][1] += a2 * b.y; acc[2][2] += a2 * b.z; acc[2][3] += a2 * b.w;
        acc[3][0] += a3 * b.x; acc[3][1] += a3 * b.y; acc[3][2] += a3 * b.z; acc[3][3] += a3 * b.w;
    }

    // -------- block amax reduce --------
    float amax = 0.f;
    #pragma unroll
    for (int i = 0; i < 4; i++)
        #pragma unroll
        for (int j = 0; j < 4; j++) amax = fmaxf(amax, fabsf(acc[i][j]));
    #pragma unroll
    for (int off = 16; off; off >>= 1)
        amax = fmaxf(amax, __shfl_xor_sync(0xffffffffu, amax, off));
    if ((tid & 31) == 0) sRT[tid >> 5] = amax;
    __syncthreads();
    float bmax = sRT[0];
    #pragma unroll
    for (int w = 1; w < 8; w++) bmax = fmaxf(bmax, sRT[w]);
    const float scale = fmaxf(bmax / 7.0f, 1e-8f);

    // -------- quantize & store --------
    char4* out4 = (char4*)(g_xq + token * (size_t)HID);
    #pragma unroll
    for (int i = 0; i < 4; i++) {
        char4 v;
        float q0 = fminf(fmaxf(rintf(acc[i][0] / scale), -8.f), 7.f);
        float q1 = fminf(fmaxf(rintf(acc[i][1] / scale), -8.f), 7.f);
        float q2 = fminf(fmaxf(rintf(acc[i][2] / scale), -8.f), 7.f);
        float q3 = fminf(fmaxf(rintf(acc[i][3] / scale), -8.f), 7.f);
        v.x = (signed char)q0; v.y = (signed char)q1;
        v.z = (signed char)q2; v.w = (signed char)q3;
        out4[((r0 + i) * 64 + c0) >> 2] = v;
    }
    if (tid == 0) g_ascale[token] = scale;
}

// ---------------------------------------------------------------------------
// Kernel 2: Y[t][o] = sum_h xq[t][h] * W[o][h]  (s8 x s8 -> s32, exact)
//           out = Y * a_scale[t] * w_scale[o]
// mma.sync.m16n8k32 s8, BM=BN=128, BK=64, 8 warps (32x64 tiles), cp.async x2
// ---------------------------------------------------------------------------
__global__ __launch_bounds__(256, 2) void gemm_kernel(
    const float* __restrict__ s0, const float* __restrict__ s1, const float* __restrict__ s2,
    float* __restrict__ out)
{
    __shared__ int8_t sA[2][BM * SROW];
    __shared__ int8_t sB[2][BN * SROW];

    const int tid  = threadIdx.x;
    const int bx   = blockIdx.x;                 // 0..95 (3 weights x 32 n-blocks)
    const int m0   = blockIdx.y * BM;
    const int wsel = bx >> 5;
    const int n0   = (bx & 31) * BN;

    const int8_t* W  = g_w + (size_t)wsel * HID * HID;
    const float*  WS = (wsel == 0) ? s0 : (wsel == 1 ? s1 : s2);

    const int8_t* Ag = g_xq + (size_t)m0 * HID;
    const int8_t* Bg = W    + (size_t)n0 * HID;

    const uint32_t sA0 = (uint32_t)__cvta_generic_to_shared(&sA[0][0]);
    const uint32_t sB0 = (uint32_t)__cvta_generic_to_shared(&sB[0][0]);

    auto load_stage = [&](int s, int k0) {
        #pragma unroll
        for (int i = 0; i < 2; i++) {
            int c   = tid + i * 256;             // 0..511
            int row = c >> 2;
            int col = (c & 3) << 4;
            uint32_t da = sA0 + (uint32_t)(s * (BM * SROW) + row * SROW + col);
            const int8_t* pa = Ag + (size_t)row * HID + k0 + col;
            asm volatile("cp.async.cg.shared.global [%0], [%1], 16;\n" :: "r"(da), "l"(pa));
            uint32_t db = sB0 + (uint32_t)(s * (BN * SROW) + row * SROW + col);
            const int8_t* pb = Bg + (size_t)row * HID + k0 + col;
            asm volatile("cp.async.cg.shared.global [%0], [%1], 16;\n" :: "r"(db), "l"(pb));
        }
        asm volatile("cp.async.commit_group;\n" ::: "memory");
    };

    const int warp  = tid >> 5, lane = tid & 31;
    const int wm    = warp >> 1, wn = warp & 1;
    const int mbase = wm * 32,   nbase = wn * 64;
    const int group = lane >> 2, tig = lane & 3;

    int acc[2][8][4];
    #pragma unroll
    for (int im = 0; im < 2; im++)
        #pragma unroll
        for (int jn = 0; jn < 8; jn++)
            #pragma unroll
            for (int q = 0; q < 4; q++) acc[im][jn][q] = 0;

    load_stage(0, 0);

    const int KT = HID / BK;                     // 64
    for (int kt = 0; kt < KT; kt++) {
        if (kt + 1 < KT) {
            load_stage((kt + 1) & 1, (kt + 1) * BK);
            asm volatile("cp.async.wait_group 1;\n" ::: "memory");
        } else {
            asm volatile("cp.async.wait_group 0;\n" ::: "memory");
        }
        __syncthreads();

        const int8_t* a_s = sA[kt & 1];
        const int8_t* b_s = sB[kt & 1];

        #pragma unroll
        for (int kk = 0; kk < 2; kk++) {
            const int ko = kk * 32;
            uint32_t af[2][4], bf[8][2];
            #pragma unroll
            for (int im = 0; im < 2; im++) {
                const int8_t* base = a_s + (mbase + im * 16 + group) * SROW + ko + tig * 4;
                af[im][0] = *(const uint32_t*)(base);
                af[im][1] = *(const uint32_t*)(base + 8 * SROW);
                af[im][2] = *(const uint32_t*)(base + 16);
                af[im][3] = *(const uint32_t*)(base + 8 * SROW + 16);
            }
            #pragma unroll
            for (int jn = 0; jn < 8; jn++) {
                const int8_t* base = b_s + (nbase + jn * 8 + group) * SROW + ko + tig * 4;
                bf[jn][0] = *(const uint32_t*)(base);
                bf[jn][1] = *(const uint32_t*)(base + 16);
            }
            #pragma unroll
            for (int im = 0; im < 2; im++)
                #pragma unroll
                for (int jn = 0; jn < 8; jn++)
                    asm volatile(
                        "mma.sync.aligned.m16n8k32.row.col.s32.s8.s8.s32 "
                        "{%0,%1,%2,%3},{%4,%5,%6,%7},{%8,%9},{%0,%1,%2,%3};\n"
                        : "+r"(acc[im][jn][0]), "+r"(acc[im][jn][1]),
                          "+r"(acc[im][jn][2]), "+r"(acc[im][jn][3])
                        : "r"(af[im][0]), "r"(af[im][1]), "r"(af[im][2]), "r"(af[im][3]),
                          "r"(bf[jn][0]), "r"(bf[jn][1]));
        }
        __syncthreads();
    }

    // -------- epilogue: dequant + store --------
    float* obase = out + (size_t)wsel * TOK * HID;
    #pragma unroll
    for (int im = 0; im < 2; im++) {
        const int t   = m0 + mbase + im * 16 + group;
        const float sa0 = g_ascale[t];
        const float sa1 = g_ascale[t + 8];
        #pragma unroll
        for (int jn = 0; jn < 8; jn++) {
            const int nl = n0 + nbase + jn * 8 + tig * 2;
            const float ws0 = WS[nl], ws1 = WS[nl + 1];
            float2 v0, v1;
            v0.x = (float)acc[im][jn][0] * sa0 * ws0;
            v0.y = (float)acc[im][jn][1] * sa0 * ws1;
            v1.x = (float)acc[im][jn][2] * sa1 * ws0;
            v1.y = (float)acc[im][jn][3] * sa1 * ws1;
            *(float2*)(obase + (size_t)t * HID + nl)       = v0;
            *(float2*)(obase + (size_t)(t + 8) * HID + nl) = v1;
        }
    }
}

// ---------------------------------------------------------------------------
extern "C" void kernel_launch(void* const* d_in, const int* in_sizes, int n_in,
                              void* d_out, int out_size)
{
    const float* hs = (const float*)d_in[0];
    const float* lt = (const float*)d_in[1];
    const float* rt = (const float*)d_in[2];
    const void*  wq = d_in[3];
    const float* sq = (const float*)d_in[4];
    const void*  wk = d_in[5];
    const float* sk = (const float*)d_in[6];
    const void*  wv = d_in[7];
    const float* sv = (const float*)d_in[8];
    float* out = (float*)d_out;

    detect_dtype_kernel<<<1, 32>>>((const unsigned int*)wq);

    dim3 cgrid((HID * HID) / 4 / 256, 3);
    convert_weights_kernel<<<cgrid, 256>>>(wq, wk, wv);

    transform_quant_kernel<<<TOK, 256>>>(hs, lt, rt);

    dim3 grid(96, 64);   // x: 3 weights x 32 n-blocks (n fastest for A reuse in L2)
    gemm_kernel<<<grid, 256>>>(sq, sk, sv, out);
}

// round 8
// speedup vs baseline: 5.6533x; 5.6533x over previous
#include <cuda_runtime.h>
#include <cuda_bf16.h>
#include <cstdint>

#define HID  4096
#define TOK  8192

// Arch-feature gate: tcgen05 exists only in the compute_103a / compute_100a pass.
#if defined(__CUDA_ARCH__) && (defined(__CUDA_ARCH_FEAT_SM103_ALL) || defined(__CUDA_ARCH_FEAT_SM100_ALL))
#define TC_OK 1
#else
#define TC_OK 0
#endif

// ---------------- tcgen05 GEMM tile config (bf16, kind::f16, cg1) ----------
#define BM     128
#define BN     256
#define BKE    64              // K elements per stage (bf16) = 128 bytes/row
#define NK     (HID / BKE)     // 64 k-iterations
#define STAGES 4

#define A_STG  (BM * 128)      // 16384 B
#define B_STG  (BN * 128)      // 32768 B
#define SM_MBAR  0                              // NK mbarriers * 8B = 512
#define SM_TPTR  512
#define SM_WS    1024                           // 256 floats
#define SM_A     2048
#define SM_B     (SM_A + STAGES * A_STG)        // 67584
#define SM_END   (SM_B + STAGES * B_STG)        // 198656
#define SMEM_DYN (SM_END + 1024)

// ---------------- legacy fallback GEMM config ------------------------------
#define LBM   128
#define LBN   128
#define LBK   64
#define LSROW 80

// Scratch (static device globals: allocation-guard safe)
__device__ int8_t         g_xq[(size_t)TOK * HID];        // int8 activations (legacy)
__device__ __nv_bfloat16  g_xbf[(size_t)TOK * HID];       // bf16 activations (tcgen05)
__device__ float          g_ascale[TOK];
__device__ int8_t         g_w[(size_t)3 * HID * HID];     // int8 weights (legacy)
__device__ __nv_bfloat16  g_wbf[(size_t)3 * HID * HID];   // bf16 weights (tcgen05)
__device__ int            g_dtype_flag;                   // 0=i8 1=i32 2=f32 3=bf16

// ---------------- PTX helpers ----------------
__device__ __forceinline__ uint32_t smem_u32(const void* p) {
    uint32_t a;
    asm("{ .reg .u64 t; cvta.to.shared.u64 t, %1; cvt.u32.u64 %0, t; }" : "=r"(a) : "l"(p));
    return a;
}
__device__ __forceinline__ uint32_t elect_one() {
    uint32_t pred;
    asm volatile("{ .reg .pred p; elect.sync _|p, 0xFFFFFFFF; selp.b32 %0, 1, 0, p; }" : "=r"(pred));
    return pred;
}
#define MBARRIER_INIT(mbar, cnt) \
    asm volatile("mbarrier.init.shared.b64 [%0], %1;" :: "r"(mbar), "r"(cnt) : "memory")
#define MBARRIER_WAIT_P0(mbar) do {                                               \
    uint32_t _m = (mbar); uint32_t _done;                                         \
    asm volatile("{ .reg .pred p; mbarrier.try_wait.parity.acquire.cta.shared::cta.b64 p, [%1], 0; " \
                 "selp.b32 %0, 1, 0, p; }" : "=r"(_done) : "r"(_m) : "memory");   \
    if (!_done) {                                                                 \
        asm volatile("{ .reg .pred P1; WL_%=: "                                   \
            "mbarrier.try_wait.parity.acquire.cta.shared::cta.b64 P1, [%0], 0, 0x989680; " \
            "@P1 bra.uni WD_%=; bra.uni WL_%=; WD_%=: }" :: "r"(_m) : "memory");  \
    } } while (0)

#if TC_OK
#define TCGEN05_ALLOC(dst, n) \
    asm volatile("tcgen05.alloc.cta_group::1.sync.aligned.shared::cta.b32 [%0], %1;" \
                 :: "r"(dst), "r"(n) : "memory")
#define TCGEN05_DEALLOC(t, n) \
    asm volatile("tcgen05.dealloc.cta_group::1.sync.aligned.b32 %0, %1;" :: "r"(t), "r"(n))
#define TCGEN05_RELINQ() \
    asm volatile("tcgen05.relinquish_alloc_permit.cta_group::1.sync.aligned;")
#define TCGEN05_COMMIT(mbar) \
    asm volatile("tcgen05.commit.cta_group::1.mbarrier::arrive::one.shared::cluster.b64 [%0];" \
                 :: "r"(mbar) : "memory")
#define TCGEN05_FENCE_AFTER()  asm volatile("tcgen05.fence::after_thread_sync;" ::: "memory")
#define TCGEN05_WAIT_LD()      asm volatile("tcgen05.wait::ld.sync.aligned;" ::: "memory")
#define LD_TM_X32(r, addr) \
    asm volatile("tcgen05.ld.sync.aligned.32x32b.x32.b32 " \
        "{%0,%1,%2,%3,%4,%5,%6,%7,%8,%9,%10,%11,%12,%13,%14,%15," \
        "%16,%17,%18,%19,%20,%21,%22,%23,%24,%25,%26,%27,%28,%29,%30,%31}, [%32];" \
        : "=r"((r)[0]),"=r"((r)[1]),"=r"((r)[2]),"=r"((r)[3]),"=r"((r)[4]),"=r"((r)[5]), \
          "=r"((r)[6]),"=r"((r)[7]),"=r"((r)[8]),"=r"((r)[9]),"=r"((r)[10]),"=r"((r)[11]), \
          "=r"((r)[12]),"=r"((r)[13]),"=r"((r)[14]),"=r"((r)[15]),"=r"((r)[16]),"=r"((r)[17]), \
          "=r"((r)[18]),"=r"((r)[19]),"=r"((r)[20]),"=r"((r)[21]),"=r"((r)[22]),"=r"((r)[23]), \
          "=r"((r)[24]),"=r"((r)[25]),"=r"((r)[26]),"=r"((r)[27]),"=r"((r)[28]),"=r"((r)[29]), \
          "=r"((r)[30]),"=r"((r)[31]) : "r"(addr))

// SW128 smem descriptor: version=1 (Blackwell), layout=SW128, SBO=64, LBO=1
static __device__ __forceinline__ uint64_t make_desc_sw128(uint32_t addr) {
    const uint64_t base = (uint64_t(2) << 61) | (uint64_t(1) << 46) |
                          (uint64_t(64) << 32) | (uint64_t(1) << 16);
    return base | ((uint64_t)(addr >> 4) & 0x3FFF);
}
// kind::f16 idesc: dtype=F32(1<<4), atype=BF16(1<<7), btype=BF16(1<<10), N, M
#define IDESC_BF16 ((1u << 4) | (1u << 7) | (1u << 10) | ((BN / 8) << 17) | ((BM / 16) << 24))

__device__ __forceinline__ void mma_bf16_ss(uint32_t d, uint64_t ad, uint64_t bd,
                                            uint32_t idesc, uint32_t en) {
    asm volatile("{ .reg .pred p; setp.ne.u32 p, %5, 0; "
                 "tcgen05.mma.cta_group::1.kind::f16 [%0], %1, %2, %3, {%4,%4,%4,%4}, p; }"
                 :: "r"(d), "l"(ad), "l"(bd), "r"(idesc), "r"(0u), "r"(en) : "memory");
}
#endif  // TC_OK

// ---------------------------------------------------------------------------
// Kernel 0a: sniff the harness's dtype for the int8 weight tensors.
// ---------------------------------------------------------------------------
__global__ void detect_dtype_kernel(const unsigned int* __restrict__ w)
{
    const int lane = threadIdx.x;
    int vi8 = 0, vi32 = 0, vf32 = 0, vbf = 0;
    #pragma unroll
    for (int i = 0; i < 8; i++) {
        unsigned int u = w[lane + i * 32];
        int s = (int)u;
        if (s >= -8 && s <= 7) vi32++;
        float f = __uint_as_float(u);
        if (f == rintf(f) && fabsf(f) <= 8.f) vf32++;
        bool ok8 = true;
        #pragma unroll
        for (int b = 0; b < 4; b++) {
            int by = (int)(signed char)(u >> (8 * b));
            if (by < -8 || by > 7) ok8 = false;
        }
        vi8 += ok8 ? 1 : 0;
        bool okb = true;
        #pragma unroll
        for (int h = 0; h < 2; h++) {
            __nv_bfloat16_raw r; r.x = (unsigned short)(u >> (16 * h));
            float fb = __bfloat162float(__nv_bfloat16(r));
            if (!(fb == rintf(fb) && fabsf(fb) <= 8.f)) okb = false;
        }
        vbf += okb ? 1 : 0;
    }
    vi8  = __reduce_add_sync(0xffffffffu, vi8);
    vi32 = __reduce_add_sync(0xffffffffu, vi32);
    vf32 = __reduce_add_sync(0xffffffffu, vf32);
    vbf  = __reduce_add_sync(0xffffffffu, vbf);
    if (lane == 0) {
        int f;
        if      (vi32 >= 240) f = 1;
        else if (vi8  >= 240) f = 0;
        else if (vf32 >= 240) f = 2;
        else                  f = 3;
        g_dtype_flag = f;
    }
}

// ---------------------------------------------------------------------------
// Kernel 0b: normalize the three weight tensors into scratch
// (int8 for legacy path, bf16 for tcgen05 path — per compiled arch).
// ---------------------------------------------------------------------------
__global__ __launch_bounds__(256) void convert_weights_kernel(
    const void* __restrict__ w0, const void* __restrict__ w1, const void* __restrict__ w2)
{
    const void* src = (blockIdx.y == 0) ? w0 : (blockIdx.y == 1 ? w1 : w2);
    const size_t i = (size_t)blockIdx.x * blockDim.x + threadIdx.x;   // 4-elem group
    const int flag = g_dtype_flag;

    float f0, f1, f2, f3;
    if (flag == 0) {
        char4 t = ((const char4*)src)[i];
        f0 = t.x; f1 = t.y; f2 = t.z; f3 = t.w;
    } else if (flag == 1) {
        int4 t = ((const int4*)src)[i];
        f0 = (float)t.x; f1 = (float)t.y; f2 = (float)t.z; f3 = (float)t.w;
    } else if (flag == 2) {
        float4 t = ((const float4*)src)[i];
        f0 = rintf(t.x); f1 = rintf(t.y); f2 = rintf(t.z); f3 = rintf(t.w);
    } else {
        const __nv_bfloat162* p = (const __nv_bfloat162*)src;
        __nv_bfloat162 a = p[i * 2], b = p[i * 2 + 1];
        f0 = rintf(__bfloat162float(a.x)); f1 = rintf(__bfloat162float(a.y));
        f2 = rintf(__bfloat162float(b.x)); f3 = rintf(__bfloat162float(b.y));
    }
#if TC_OK
    __nv_bfloat162* dst = (__nv_bfloat162*)(g_wbf + (size_t)blockIdx.y * HID * HID);
    dst[i * 2]     = __floats2bfloat162_rn(f0, f1);
    dst[i * 2 + 1] = __floats2bfloat162_rn(f2, f3);
#else
    char4 v;
    v.x = (signed char)(int)f0; v.y = (signed char)(int)f1;
    v.z = (signed char)(int)f2; v.w = (signed char)(int)f3;
    ((char4*)(g_w + (size_t)blockIdx.y * HID * HID))[i] = v;
#endif
}

// ---------------------------------------------------------------------------
// Kernel 1: per-token 64x64 transform (fp32) + amax + int4-range quantize
// ---------------------------------------------------------------------------
__global__ __launch_bounds__(256) void transform_quant_kernel(
    const float* __restrict__ hs,
    const float* __restrict__ lt,
    const float* __restrict__ rt)
{
    __shared__ float sX[4096];
    __shared__ float sRT[4096];
    __shared__ float sLT[4096];

    const int tid   = threadIdx.x;
    const long token = blockIdx.x;
    const float* x = hs + token * (long)HID;

    #pragma unroll
    for (int i = 0; i < 4; i++) {
        int idx = tid + i * 256;
        ((float4*)sX)[idx]  = ((const float4*)x)[idx];
        ((float4*)sRT)[idx] = ((const float4*)rt)[idx];
        ((float4*)sLT)[idx] = ((const float4*)lt)[idx];
    }
    __syncthreads();

    const int ty = tid >> 4;
    const int tx = tid & 15;
    const int r0 = ty * 4;
    const int c0 = tx * 4;

    float acc[4][4];
    #pragma unroll
    for (int i = 0; i < 4; i++)
        #pragma unroll
        for (int j = 0; j < 4; j++) acc[i][j] = 0.f;

    #pragma unroll 8
    for (int r = 0; r < 64; r++) {
        float4 b = *(const float4*)&sRT[r * 64 + c0];
        float a0 = sX[(r0 + 0) * 64 + r];
        float a1 = sX[(r0 + 1) * 64 + r];
        float a2 = sX[(r0 + 2) * 64 + r];
        float a3 = sX[(r0 + 3) * 64 + r];
        acc[0][0] += a0 * b.x; acc[0][1] += a0 * b.y; acc[0][2] += a0 * b.z; acc[0][3] += a0 * b.w;
        acc[1][0] += a1 * b.x; acc[1][1] += a1 * b.y; acc[1][2] += a1 * b.z; acc[1][3] += a1 * b.w;
        acc[2][0] += a2 * b.x; acc[2][1] += a2 * b.y; acc[2][2] += a2 * b.z; acc[2][3] += a2 * b.w;
        acc[3][0] += a3 * b.x; acc[3][1] += a3 * b.y; acc[3][2] += a3 * b.z; acc[3][3] += a3 * b.w;
    }
    __syncthreads();

    #pragma unroll
    for (int i = 0; i < 4; i++)
        *(float4*)&sX[(r0 + i) * 64 + c0] =
            make_float4(acc[i][0], acc[i][1], acc[i][2], acc[i][3]);
    __syncthreads();

    #pragma unroll
    for (int i = 0; i < 4; i++)
        #pragma unroll
        for (int j = 0; j < 4; j++) acc[i][j] = 0.f;

    #pragma unroll 8
    for (int l = 0; l < 64; l++) {
        float4 b = *(const float4*)&sX[l * 64 + c0];
        float a0 = sLT[(r0 + 0) * 64 + l];
        float a1 = sLT[(r0 + 1) * 64 + l];
        float a2 = sLT[(r0 + 2) * 64 + l];
        float a3 = sLT[(r0 + 3) * 64 + l];
        acc[0][0] += a0 * b.x; acc[0][1] += a0 * b.y; acc[0][2] += a0 * b.z; acc[0][3] += a0 * b.w;
        acc[1][0] += a1 * b.x; acc[1][1] += a1 * b.y; acc[1][2] += a1 * b.z; acc[1][3] += a1 * b.w;
        acc[2][0] += a2 * b.x; acc[2][1] += a2 * b.y; acc[2][2] += a2 * b.z; acc[2][3] += a2 * b.w;
        acc[3][0] += a3 * b.x; acc[3][1] += a3 * b.y; acc[3][2] += a3 * b.z; acc[3][3] += a3 * b.w;
    }

    float amax = 0.f;
    #pragma unroll
    for (int i = 0; i < 4; i++)
        #pragma unroll
        for (int j = 0; j < 4; j++) amax = fmaxf(amax, fabsf(acc[i][j]));
    #pragma unroll
    for (int off = 16; off; off >>= 1)
        amax = fmaxf(amax, __shfl_xor_sync(0xffffffffu, amax, off));
    if ((tid & 31) == 0) sRT[tid >> 5] = amax;
    __syncthreads();
    float bmax = sRT[0];
    #pragma unroll
    for (int w = 1; w < 8; w++) bmax = fmaxf(bmax, sRT[w]);
    const float scale = fmaxf(bmax / 7.0f, 1e-8f);

    #pragma unroll
    for (int i = 0; i < 4; i++) {
        float q0 = fminf(fmaxf(rintf(acc[i][0] / scale), -8.f), 7.f);
        float q1 = fminf(fmaxf(rintf(acc[i][1] / scale), -8.f), 7.f);
        float q2 = fminf(fmaxf(rintf(acc[i][2] / scale), -8.f), 7.f);
        float q3 = fminf(fmaxf(rintf(acc[i][3] / scale), -8.f), 7.f);
#if TC_OK
        __nv_bfloat162* ob = (__nv_bfloat162*)(g_xbf + token * (size_t)HID);
        int e = (r0 + i) * 64 + c0;
        ob[e / 2]     = __floats2bfloat162_rn(q0, q1);
        ob[e / 2 + 1] = __floats2bfloat162_rn(q2, q3);
#else
        char4 v;
        v.x = (signed char)q0; v.y = (signed char)q1;
        v.z = (signed char)q2; v.w = (signed char)q3;
        ((char4*)(g_xq + token * (size_t)HID))[((r0 + i) * 64 + c0) >> 2] = v;
#endif
    }
    if (tid == 0) g_ascale[token] = scale;
}

// ---------------------------------------------------------------------------
// Kernel 2a: tcgen05 bf16 GEMM (active only in the sm_103a pass).
// Y[t][o] = sum_h xq[t][h]*w[o][h] in f32 (exact ints), dequant, store.
// ---------------------------------------------------------------------------
__global__ __launch_bounds__(256, 1) void gemm_tc_kernel(
    const float* __restrict__ s0, const float* __restrict__ s1, const float* __restrict__ s2,
    float* __restrict__ out)
{
#if TC_OK
    extern __shared__ char dsm[];
    const uint32_t sbase = (smem_u32(dsm) + 1023u) & ~1023u;

    const int tid  = threadIdx.x;
    const int warp = tid >> 5;
    const int lane = tid & 31;

    const int wsel = blockIdx.x >> 4;            // 0..2
    const int n0   = (blockIdx.x & 15) * BN;     // 16 n-blocks
    const int m0   = blockIdx.y * BM;            // 64 m-blocks

    const __nv_bfloat16* Ag = g_xbf + (size_t)m0 * HID;
    const __nv_bfloat16* Bg = g_wbf + (size_t)wsel * HID * HID + (size_t)n0 * HID;
    const float* WS = (wsel == 0) ? s0 : (wsel == 1 ? s1 : s2);

    if (warp == 0) {
        TCGEN05_ALLOC(sbase + SM_TPTR, 512);
        TCGEN05_RELINQ();
    }
    if (tid == 0) {
        for (int s = 0; s < NK; s++) MBARRIER_INIT(sbase + SM_MBAR + s * 8, 1);
    }
    {
        float* sws = (float*)(dsm + (sbase - smem_u32(dsm)) + SM_WS);
        sws[tid] = WS[n0 + tid];
    }
    __syncthreads();
    uint32_t tmem_base;
    asm volatile("ld.shared.b32 %0, [%1];" : "=r"(tmem_base) : "r"(sbase + SM_TPTR));

    // one stage = A 128 rows x 128B + B 256 rows x 128B, SW128-swizzled
    auto load_stage = [&](int slot, int kt) {
        const int k0 = kt * BKE;                  // bf16 element offset
        const uint32_t abase = sbase + SM_A + slot * A_STG;
        const uint32_t bbase = sbase + SM_B + slot * B_STG;
        const char* ab = (const char*)Ag + (size_t)k0 * 2;
        const char* bb = (const char*)Bg + (size_t)k0 * 2;
        #pragma unroll
        for (int i = 0; i < 4; i++) {             // A: 1024 granules of 16B
            int c = tid + i * 256;
            int row = c >> 3, col = c & 7;
            uint32_t d = abase + (uint32_t)(row * 128 + ((col ^ (row & 7)) << 4));
            const char* p = ab + (size_t)row * (HID * 2) + col * 16;
            asm volatile("cp.async.cg.shared.global [%0], [%1], 16;" :: "r"(d), "l"(p));
        }
        #pragma unroll
        for (int i = 0; i < 8; i++) {             // B: 2048 granules of 16B
            int c = tid + i * 256;
            int row = c >> 3, col = c & 7;
            uint32_t d = bbase + (uint32_t)(row * 128 + ((col ^ (row & 7)) << 4));
            const char* p = bb + (size_t)row * (HID * 2) + col * 16;
            asm volatile("cp.async.cg.shared.global [%0], [%1], 16;" :: "r"(d), "l"(p));
        }
        asm volatile("cp.async.commit_group;" ::: "memory");
    };

    load_stage(0, 0);
    load_stage(1, 1);

    const uint32_t idesc = IDESC_BF16;
    for (int kt = 0; kt < NK; kt++) {
        if (kt + 2 < NK) {
            if (kt >= 2) MBARRIER_WAIT_P0(sbase + SM_MBAR + (kt - 2) * 8);
            load_stage((kt + 2) & (STAGES - 1), kt + 2);
        }
        if (kt + 2 < NK)      asm volatile("cp.async.wait_group 2;" ::: "memory");
        else if (kt + 1 < NK) asm volatile("cp.async.wait_group 1;" ::: "memory");
        else                  asm volatile("cp.async.wait_group 0;" ::: "memory");
        asm volatile("fence.proxy.async.shared::cta;" ::: "memory");
        __syncthreads();

        if (warp == 0) {
            TCGEN05_FENCE_AFTER();
            if (elect_one()) {
                const int slot = kt & (STAGES - 1);
                uint64_t ad = make_desc_sw128(sbase + SM_A + slot * A_STG);
                uint64_t bd = make_desc_sw128(sbase + SM_B + slot * B_STG);
                #pragma unroll
                for (int c = 0; c < 4; c++)       // 4 x K=16 bf16 chunks (32B = +2 units)
                    mma_bf16_ss(tmem_base, ad + c * 2, bd + c * 2, idesc,
                                (kt > 0 || c > 0) ? 1u : 0u);
                TCGEN05_COMMIT(sbase + SM_MBAR + kt * 8);
            }
        }
    }

    MBARRIER_WAIT_P0(sbase + SM_MBAR + (NK - 1) * 8);
    TCGEN05_FENCE_AFTER();

    const int  rsub = (warp & 3) * 32 + lane;     // D row (subpartition-local)
    const int  half = warp >> 2;                  // column half 0/1
    const int  t    = m0 + rsub;
    const float sa  = g_ascale[t];
    float* orow = out + (size_t)wsel * TOK * HID + (size_t)t * HID + n0 + half * 128;
    const float* sws = (const float*)(dsm + (sbase - smem_u32(dsm)) + SM_WS) + half * 128;

    #pragma unroll
    for (int c = 0; c < 4; c++) {
        uint32_t r[32];
        LD_TM_X32(r, tmem_base + half * 128 + c * 32);
        TCGEN05_WAIT_LD();
        #pragma unroll
        for (int j = 0; j < 32; j += 4) {
            float4 v;
            v.x = __uint_as_float(r[j + 0]) * sa * sws[c * 32 + j + 0];
            v.y = __uint_as_float(r[j + 1]) * sa * sws[c * 32 + j + 1];
            v.z = __uint_as_float(r[j + 2]) * sa * sws[c * 32 + j + 2];
            v.w = __uint_as_float(r[j + 3]) * sa * sws[c * 32 + j + 3];
            *(float4*)(orow + c * 32 + j) = v;
        }
    }
    __syncthreads();
    if (warp == 0) TCGEN05_DEALLOC(tmem_base, 512);
#endif  // TC_OK
}

// ---------------------------------------------------------------------------
// Kernel 2b: legacy mma.sync s8 GEMM (active only in the base-arch pass).
// Identical to the round-5 passing kernel.
// ---------------------------------------------------------------------------
__global__ __launch_bounds__(256, 2) void gemm_legacy_kernel(
    const float* __restrict__ s0, const float* __restrict__ s1, const float* __restrict__ s2,
    float* __restrict__ out)
{
#if !TC_OK
    __shared__ int8_t sA[2][LBM * LSROW];
    __shared__ int8_t sB[2][LBN * LSROW];

    const int tid  = threadIdx.x;
    const int bx   = blockIdx.x;
    const int m0   = blockIdx.y * LBM;
    const int wsel = bx >> 5;
    const int n0   = (bx & 31) * LBN;

    const int8_t* W  = g_w + (size_t)wsel * HID * HID;
    const float*  WS = (wsel == 0) ? s0 : (wsel == 1 ? s1 : s2);

    const int8_t* Ag = g_xq + (size_t)m0 * HID;
    const int8_t* Bg = W    + (size_t)n0 * HID;

    const uint32_t sA0 = (uint32_t)__cvta_generic_to_shared(&sA[0][0]);
    const uint32_t sB0 = (uint32_t)__cvta_generic_to_shared(&sB[0][0]);

    auto load_stage = [&](int s, int k0) {
        #pragma unroll
        for (int i = 0; i < 2; i++) {
            int c   = tid + i * 256;
            int row = c >> 2;
            int col = (c & 3) << 4;
            uint32_t da = sA0 + (uint32_t)(s * (LBM * LSROW) + row * LSROW + col);
            const int8_t* pa = Ag + (size_t)row * HID + k0 + col;
            asm volatile("cp.async.cg.shared.global [%0], [%1], 16;\n" :: "r"(da), "l"(pa));
            uint32_t db = sB0 + (uint32_t)(s * (LBN * LSROW) + row * LSROW + col);
            const int8_t* pb = Bg + (size_t)row * HID + k0 + col;
            asm volatile("cp.async.cg.shared.global [%0], [%1], 16;\n" :: "r"(db), "l"(pb));
        }
        asm volatile("cp.async.commit_group;\n" ::: "memory");
    };

    const int warp  = tid >> 5, lane = tid & 31;
    const int wm    = warp >> 1, wn = warp & 1;
    const int mbase = wm * 32,   nbase = wn * 64;
    const int group = lane >> 2, tig = lane & 3;

    int acc[2][8][4];
    #pragma unroll
    for (int im = 0; im < 2; im++)
        #pragma unroll
        for (int jn = 0; jn < 8; jn++)
            #pragma unroll
            for (int q = 0; q < 4; q++) acc[im][jn][q] = 0;

    load_stage(0, 0);

    const int KT = HID / LBK;
    for (int kt = 0; kt < KT; kt++) {
        if (kt + 1 < KT) {
            load_stage((kt + 1) & 1, (kt + 1) * LBK);
            asm volatile("cp.async.wait_group 1;\n" ::: "memory");
        } else {
            asm volatile("cp.async.wait_group 0;\n" ::: "memory");
        }
        __syncthreads();

        const int8_t* a_s = sA[kt & 1];
        const int8_t* b_s = sB[kt & 1];

        #pragma unroll
        for (int kk = 0; kk < 2; kk++) {
            const int ko = kk * 32;
            uint32_t af[2][4], bf[8][2];
            #pragma unroll
            for (int im = 0; im < 2; im++) {
                const int8_t* base = a_s + (mbase + im * 16 + group) * LSROW + ko + tig * 4;
                af[im][0] = *(const uint32_t*)(base);
                af[im][1] = *(const uint32_t*)(base + 8 * LSROW);
                af[im][2] = *(const uint32_t*)(base + 16);
                af[im][3] = *(const uint32_t*)(base + 8 * LSROW + 16);
            }
            #pragma unroll
            for (int jn = 0; jn < 8; jn++) {
                const int8_t* base = b_s + (nbase + jn * 8 + group) * LSROW + ko + tig * 4;
                bf[jn][0] = *(const uint32_t*)(base);
                bf[jn][1] = *(const uint32_t*)(base + 16);
            }
            #pragma unroll
            for (int im = 0; im < 2; im++)
                #pragma unroll
                for (int jn = 0; jn < 8; jn++)
                    asm volatile(
                        "mma.sync.aligned.m16n8k32.row.col.s32.s8.s8.s32 "
                        "{%0,%1,%2,%3},{%4,%5,%6,%7},{%8,%9},{%0,%1,%2,%3};\n"
                        : "+r"(acc[im][jn][0]), "+r"(acc[im][jn][1]),
                          "+r"(acc[im][jn][2]), "+r"(acc[im][jn][3])
                        : "r"(af[im][0]), "r"(af[im][1]), "r"(af[im][2]), "r"(af[im][3]),
                          "r"(bf[jn][0]), "r"(bf[jn][1]));
        }
        __syncthreads();
    }

    float* obase = out + (size_t)wsel * TOK * HID;
    #pragma unroll
    for (int im = 0; im < 2; im++) {
        const int t   = m0 + mbase + im * 16 + group;
        const float sa0 = g_ascale[t];
        const float sa1 = g_ascale[t + 8];
        #pragma unroll
        for (int jn = 0; jn < 8; jn++) {
            const int nl = n0 + nbase + jn * 8 + tig * 2;
            const float ws0 = WS[nl], ws1 = WS[nl + 1];
            float2 v0, v1;
            v0.x = (float)acc[im][jn][0] * sa0 * ws0;
            v0.y = (float)acc[im][jn][1] * sa0 * ws1;
            v1.x = (float)acc[im][jn][2] * sa1 * ws0;
            v1.y = (float)acc[im][jn][3] * sa1 * ws1;
            *(float2*)(obase + (size_t)t * HID + nl)       = v0;
            *(float2*)(obase + (size_t)(t + 8) * HID + nl) = v1;
        }
    }
#endif  // !TC_OK
}

// ---------------------------------------------------------------------------
extern "C" void kernel_launch(void* const* d_in, const int* in_sizes, int n_in,
                              void* d_out, int out_size)
{
    const float* hs = (const float*)d_in[0];
    const float* lt = (const float*)d_in[1];
    const float* rt = (const float*)d_in[2];
    const void*  wq = d_in[3];
    const float* sq = (const float*)d_in[4];
    const void*  wk = d_in[5];
    const float* sk = (const float*)d_in[6];
    const void*  wv = d_in[7];
    const float* sv = (const float*)d_in[8];
    float* out = (float*)d_out;

    detect_dtype_kernel<<<1, 32>>>((const unsigned int*)wq);

    dim3 cgrid((HID * HID) / 4 / 256, 3);
    convert_weights_kernel<<<cgrid, 256>>>(wq, wk, wv);

    transform_quant_kernel<<<TOK, 256>>>(hs, lt, rt);

    // tcgen05 path (no-op body if only the base-arch SASS was built)
    cudaFuncSetAttribute(gemm_tc_kernel,
                         cudaFuncAttributeMaxDynamicSharedMemorySize, SMEM_DYN);
    dim3 tgrid(48, 64);
    gemm_tc_kernel<<<tgrid, 256, SMEM_DYN>>>(sq, sk, sv, out);

    // legacy path (no-op body in the sm_103a SASS)
    dim3 lgrid(96, 64);
    gemm_legacy_kernel<<<lgrid, 256>>>(sq, sk, sv, out);
}

// round 9
// speedup vs baseline: 5.6698x; 1.0029x over previous
#include <cuda_runtime.h>
#include <cuda_bf16.h>
#include <cstdint>

#define HID  4096
#define TOK  8192

// Arch-feature gate: tcgen05 exists only in the compute_103a / compute_100a pass.
#if defined(__CUDA_ARCH__) && (defined(__CUDA_ARCH_FEAT_SM103_ALL) || defined(__CUDA_ARCH_FEAT_SM100_ALL))
#define TC_OK 1
#else
#define TC_OK 0
#endif

// ---------------- tcgen05 GEMM tile config (bf16, kind::f16, cg1) ----------
#define BM     128
#define BN     256
#define BKE    64              // K elements per stage (bf16) = 128 bytes/row
#define NK     (HID / BKE)     // 64 k-iterations
#define STAGES 4

#define A_STG  (BM * 128)      // 16384 B
#define B_STG  (BN * 128)      // 32768 B
#define SM_MBAR  0                              // NK mbarriers * 8B = 512
#define SM_TPTR  512
#define SM_WS    1024                           // 256 floats
#define SM_A     2048
#define SM_B     (SM_A + STAGES * A_STG)        // 67584
#define SM_END   (SM_B + STAGES * B_STG)        // 198656
#define SMEM_DYN (SM_END + 1024)

// ---------------- legacy fallback GEMM config ------------------------------
#define LBM   128
#define LBN   128
#define LBK   64
#define LSROW 80

// Scratch (static device globals: allocation-guard safe)
__device__ int8_t         g_xq[(size_t)TOK * HID];        // int8 activations (legacy)
__device__ __nv_bfloat16  g_xbf[(size_t)TOK * HID];       // bf16 activations (tcgen05)
__device__ float          g_ascale[TOK];
__device__ int8_t         g_w[(size_t)3 * HID * HID];     // int8 weights (legacy)
__device__ __nv_bfloat16  g_wbf[(size_t)3 * HID * HID];   // bf16 weights (tcgen05)
__device__ int            g_dtype_flag;                   // 0=i8 1=i32 2=f32 3=bf16

// ---------------- PTX helpers ----------------
__device__ __forceinline__ uint32_t smem_u32(const void* p) {
    uint32_t a;
    asm("{ .reg .u64 t; cvta.to.shared.u64 t, %1; cvt.u32.u64 %0, t; }" : "=r"(a) : "l"(p));
    return a;
}
__device__ __forceinline__ uint32_t elect_one() {
    uint32_t pred;
    asm volatile("{ .reg .pred p; elect.sync _|p, 0xFFFFFFFF; selp.b32 %0, 1, 0, p; }" : "=r"(pred));
    return pred;
}
#define MBARRIER_INIT(mbar, cnt) \
    asm volatile("mbarrier.init.shared.b64 [%0], %1;" :: "r"(mbar), "r"(cnt) : "memory")
#define MBARRIER_WAIT_P0(mbar) do {                                               \
    uint32_t _m = (mbar); uint32_t _done;                                         \
    asm volatile("{ .reg .pred p; mbarrier.try_wait.parity.acquire.cta.shared::cta.b64 p, [%1], 0; " \
                 "selp.b32 %0, 1, 0, p; }" : "=r"(_done) : "r"(_m) : "memory");   \
    if (!_done) {                                                                 \
        asm volatile("{ .reg .pred P1; WL_%=: "                                   \
            "mbarrier.try_wait.parity.acquire.cta.shared::cta.b64 P1, [%0], 0, 0x989680; " \
            "@P1 bra.uni WD_%=; bra.uni WL_%=; WD_%=: }" :: "r"(_m) : "memory");  \
    } } while (0)

#if TC_OK
#define TCGEN05_ALLOC(dst, n) \
    asm volatile("tcgen05.alloc.cta_group::1.sync.aligned.shared::cta.b32 [%0], %1;" \
                 :: "r"(dst), "r"(n) : "memory")
#define TCGEN05_DEALLOC(t, n) \
    asm volatile("tcgen05.dealloc.cta_group::1.sync.aligned.b32 %0, %1;" :: "r"(t), "r"(n))
#define TCGEN05_RELINQ() \
    asm volatile("tcgen05.relinquish_alloc_permit.cta_group::1.sync.aligned;")
#define TCGEN05_COMMIT(mbar) \
    asm volatile("tcgen05.commit.cta_group::1.mbarrier::arrive::one.shared::cluster.b64 [%0];" \
                 :: "r"(mbar) : "memory")
#define TCGEN05_FENCE_AFTER()  asm volatile("tcgen05.fence::after_thread_sync;" ::: "memory")
#define TCGEN05_WAIT_LD()      asm volatile("tcgen05.wait::ld.sync.aligned;" ::: "memory")
#define LD_TM_X32(r, addr) \
    asm volatile("tcgen05.ld.sync.aligned.32x32b.x32.b32 " \
        "{%0,%1,%2,%3,%4,%5,%6,%7,%8,%9,%10,%11,%12,%13,%14,%15," \
        "%16,%17,%18,%19,%20,%21,%22,%23,%24,%25,%26,%27,%28,%29,%30,%31}, [%32];" \
        : "=r"((r)[0]),"=r"((r)[1]),"=r"((r)[2]),"=r"((r)[3]),"=r"((r)[4]),"=r"((r)[5]), \
          "=r"((r)[6]),"=r"((r)[7]),"=r"((r)[8]),"=r"((r)[9]),"=r"((r)[10]),"=r"((r)[11]), \
          "=r"((r)[12]),"=r"((r)[13]),"=r"((r)[14]),"=r"((r)[15]),"=r"((r)[16]),"=r"((r)[17]), \
          "=r"((r)[18]),"=r"((r)[19]),"=r"((r)[20]),"=r"((r)[21]),"=r"((r)[22]),"=r"((r)[23]), \
          "=r"((r)[24]),"=r"((r)[25]),"=r"((r)[26]),"=r"((r)[27]),"=r"((r)[28]),"=r"((r)[29]), \
          "=r"((r)[30]),"=r"((r)[31]) : "r"(addr))

// SW128 smem descriptor: version=1 (Blackwell), layout=SW128, SBO=64, LBO=1
static __device__ __forceinline__ uint64_t make_desc_sw128(uint32_t addr) {
    const uint64_t base = (uint64_t(2) << 61) | (uint64_t(1) << 46) |
                          (uint64_t(64) << 32) | (uint64_t(1) << 16);
    return base | ((uint64_t)(addr >> 4) & 0x3FFF);
}
// kind::f16 idesc: dtype=F32(1<<4), atype=BF16(1<<7), btype=BF16(1<<10), N, M
#define IDESC_BF16 ((1u << 4) | (1u << 7) | (1u << 10) | ((BN / 8) << 17) | ((BM / 16) << 24))

__device__ __forceinline__ void mma_bf16_ss(uint32_t d, uint64_t ad, uint64_t bd,
                                            uint32_t idesc, uint32_t en) {
    asm volatile("{ .reg .pred p; setp.ne.u32 p, %5, 0; "
                 "tcgen05.mma.cta_group::1.kind::f16 [%0], %1, %2, %3, {%4,%4,%4,%4}, p; }"
                 :: "r"(d), "l"(ad), "l"(bd), "r"(idesc), "r"(0u), "r"(en) : "memory");
}
#endif  // TC_OK

// ---------------------------------------------------------------------------
// Kernel 0a: sniff the harness's dtype for the int8 weight tensors.
// ---------------------------------------------------------------------------
__global__ void detect_dtype_kernel(const unsigned int* __restrict__ w)
{
    const int lane = threadIdx.x;
    int vi8 = 0, vi32 = 0, vf32 = 0, vbf = 0;
    #pragma unroll
    for (int i = 0; i < 8; i++) {
        unsigned int u = w[lane + i * 32];
        int s = (int)u;
        if (s >= -8 && s <= 7) vi32++;
        float f = __uint_as_float(u);
        if (f == rintf(f) && fabsf(f) <= 8.f) vf32++;
        bool ok8 = true;
        #pragma unroll
        for (int b = 0; b < 4; b++) {
            int by = (int)(signed char)(u >> (8 * b));
            if (by < -8 || by > 7) ok8 = false;
        }
        vi8 += ok8 ? 1 : 0;
        bool okb = true;
        #pragma unroll
        for (int h = 0; h < 2; h++) {
            __nv_bfloat16_raw r; r.x = (unsigned short)(u >> (16 * h));
            float fb = __bfloat162float(__nv_bfloat16(r));
            if (!(fb == rintf(fb) && fabsf(fb) <= 8.f)) okb = false;
        }
        vbf += okb ? 1 : 0;
    }
    vi8  = __reduce_add_sync(0xffffffffu, vi8);
    vi32 = __reduce_add_sync(0xffffffffu, vi32);
    vf32 = __reduce_add_sync(0xffffffffu, vf32);
    vbf  = __reduce_add_sync(0xffffffffu, vbf);
    if (lane == 0) {
        int f;
        if      (vi32 >= 240) f = 1;
        else if (vi8  >= 240) f = 0;
        else if (vf32 >= 240) f = 2;
        else                  f = 3;
        g_dtype_flag = f;
    }
}

// ---------------------------------------------------------------------------
// Kernel 0b: normalize the three weight tensors into scratch
// (int8 for legacy path, bf16 for tcgen05 path — per compiled arch).
// ---------------------------------------------------------------------------
__global__ __launch_bounds__(256) void convert_weights_kernel(
    const void* __restrict__ w0, const void* __restrict__ w1, const void* __restrict__ w2)
{
    const void* src = (blockIdx.y == 0) ? w0 : (blockIdx.y == 1 ? w1 : w2);
    const size_t i = (size_t)blockIdx.x * blockDim.x + threadIdx.x;   // 4-elem group
    const int flag = g_dtype_flag;

    float f0, f1, f2, f3;
    if (flag == 0) {
        char4 t = ((const char4*)src)[i];
        f0 = t.x; f1 = t.y; f2 = t.z; f3 = t.w;
    } else if (flag == 1) {
        int4 t = ((const int4*)src)[i];
        f0 = (float)t.x; f1 = (float)t.y; f2 = (float)t.z; f3 = (float)t.w;
    } else if (flag == 2) {
        float4 t = ((const float4*)src)[i];
        f0 = rintf(t.x); f1 = rintf(t.y); f2 = rintf(t.z); f3 = rintf(t.w);
    } else {
        const __nv_bfloat162* p = (const __nv_bfloat162*)src;
        __nv_bfloat162 a = p[i * 2], b = p[i * 2 + 1];
        f0 = rintf(__bfloat162float(a.x)); f1 = rintf(__bfloat162float(a.y));
        f2 = rintf(__bfloat162float(b.x)); f3 = rintf(__bfloat162float(b.y));
    }
#if TC_OK
    __nv_bfloat162* dst = (__nv_bfloat162*)(g_wbf + (size_t)blockIdx.y * HID * HID);
    dst[i * 2]     = __floats2bfloat162_rn(f0, f1);
    dst[i * 2 + 1] = __floats2bfloat162_rn(f2, f3);
#else
    char4 v;
    v.x = (signed char)(int)f0; v.y = (signed char)(int)f1;
    v.z = (signed char)(int)f2; v.w = (signed char)(int)f3;
    ((char4*)(g_w + (size_t)blockIdx.y * HID * HID))[i] = v;
#endif
}

// ---------------------------------------------------------------------------
// Kernel 1: per-token 64x64 transform (fp32) + amax + int4-range quantize
// ---------------------------------------------------------------------------
__global__ __launch_bounds__(256) void transform_quant_kernel(
    const float* __restrict__ hs,
    const float* __restrict__ lt,
    const float* __restrict__ rt)
{
    __shared__ float sX[4096];
    __shared__ float sRT[4096];
    __shared__ float sLT[4096];

    const int tid   = threadIdx.x;
    const long token = blockIdx.x;
    const float* x = hs + token * (long)HID;

    #pragma unroll
    for (int i = 0; i < 4; i++) {
        int idx = tid + i * 256;
        ((float4*)sX)[idx]  = ((const float4*)x)[idx];
        ((float4*)sRT)[idx] = ((const float4*)rt)[idx];
        ((float4*)sLT)[idx] = ((const float4*)lt)[idx];
    }
    __syncthreads();

    const int ty = tid >> 4;
    const int tx = tid & 15;
    const int r0 = ty * 4;
    const int c0 = tx * 4;

    float acc[4][4];
    #pragma unroll
    for (int i = 0; i < 4; i++)
        #pragma unroll
        for (int j = 0; j < 4; j++) acc[i][j] = 0.f;

    #pragma unroll 8
    for (int r = 0; r < 64; r++) {
        float4 b = *(const float4*)&sRT[r * 64 + c0];
        float a0 = sX[(r0 + 0) * 64 + r];
        float a1 = sX[(r0 + 1) * 64 + r];
        float a2 = sX[(r0 + 2) * 64 + r];
        float a3 = sX[(r0 + 3) * 64 + r];
        acc[0][0] += a0 * b.x; acc[0][1] += a0 * b.y; acc[0][2] += a0 * b.z; acc[0][3] += a0 * b.w;
        acc[1][0] += a1 * b.x; acc[1][1] += a1 * b.y; acc[1][2] += a1 * b.z; acc[1][3] += a1 * b.w;
        acc[2][0] += a2 * b.x; acc[2][1] += a2 * b.y; acc[2][2] += a2 * b.z; acc[2][3] += a2 * b.w;
        acc[3][0] += a3 * b.x; acc[3][1] += a3 * b.y; acc[3][2] += a3 * b.z; acc[3][3] += a3 * b.w;
    }
    __syncthreads();

    #pragma unroll
    for (int i = 0; i < 4; i++)
        *(float4*)&sX[(r0 + i) * 64 + c0] =
            make_float4(acc[i][0], acc[i][1], acc[i][2], acc[i][3]);
    __syncthreads();

    #pragma unroll
    for (int i = 0; i < 4; i++)
        #pragma unroll
        for (int j = 0; j < 4; j++) acc[i][j] = 0.f;

    #pragma unroll 8
    for (int l = 0; l < 64; l++) {
        float4 b = *(const float4*)&sX[l * 64 + c0];
        float a0 = sLT[(r0 + 0) * 64 + l];
        float a1 = sLT[(r0 + 1) * 64 + l];
        float a2 = sLT[(r0 + 2) * 64 + l];
        float a3 = sLT[(r0 + 3) * 64 + l];
        acc[0][0] += a0 * b.x; acc[0][1] += a0 * b.y; acc[0][2] += a0 * b.z; acc[0][3] += a0 * b.w;
        acc[1][0] += a1 * b.x; acc[1][1] += a1 * b.y; acc[1][2] += a1 * b.z; acc[1][3] += a1 * b.w;
        acc[2][0] += a2 * b.x; acc[2][1] += a2 * b.y; acc[2][2] += a2 * b.z; acc[2][3] += a2 * b.w;
        acc[3][0] += a3 * b.x; acc[3][1] += a3 * b.y; acc[3][2] += a3 * b.z; acc[3][3] += a3 * b.w;
    }

    float amax = 0.f;
    #pragma unroll
    for (int i = 0; i < 4; i++)
        #pragma unroll
        for (int j = 0; j < 4; j++) amax = fmaxf(amax, fabsf(acc[i][j]));
    #pragma unroll
    for (int off = 16; off; off >>= 1)
        amax = fmaxf(amax, __shfl_xor_sync(0xffffffffu, amax, off));
    if ((tid & 31) == 0) sRT[tid >> 5] = amax;
    __syncthreads();
    float bmax = sRT[0];
    #pragma unroll
    for (int w = 1; w < 8; w++) bmax = fmaxf(bmax, sRT[w]);
    const float scale = fmaxf(bmax / 7.0f, 1e-8f);

    #pragma unroll
    for (int i = 0; i < 4; i++) {
        float q0 = fminf(fmaxf(rintf(acc[i][0] / scale), -8.f), 7.f);
        float q1 = fminf(fmaxf(rintf(acc[i][1] / scale), -8.f), 7.f);
        float q2 = fminf(fmaxf(rintf(acc[i][2] / scale), -8.f), 7.f);
        float q3 = fminf(fmaxf(rintf(acc[i][3] / scale), -8.f), 7.f);
#if TC_OK
        __nv_bfloat162* ob = (__nv_bfloat162*)(g_xbf + token * (size_t)HID);
        int e = (r0 + i) * 64 + c0;
        ob[e / 2]     = __floats2bfloat162_rn(q0, q1);
        ob[e / 2 + 1] = __floats2bfloat162_rn(q2, q3);
#else
        char4 v;
        v.x = (signed char)q0; v.y = (signed char)q1;
        v.z = (signed char)q2; v.w = (signed char)q3;
        ((char4*)(g_xq + token * (size_t)HID))[((r0 + i) * 64 + c0) >> 2] = v;
#endif
    }
    if (tid == 0) g_ascale[token] = scale;
}

// ---------------------------------------------------------------------------
// Kernel 2a: tcgen05 bf16 GEMM (active only in the sm_103a pass).
// Y[t][o] = sum_h xq[t][h]*w[o][h] in f32 (exact ints), dequant, store.
// ---------------------------------------------------------------------------
__global__ __launch_bounds__(256, 1) void gemm_tc_kernel(
    const float* __restrict__ s0, const float* __restrict__ s1, const float* __restrict__ s2,
    float* __restrict__ out)
{
#if TC_OK
    extern __shared__ char dsm[];
    const uint32_t sbase = (smem_u32(dsm) + 1023u) & ~1023u;

    const int tid  = threadIdx.x;
    const int warp = tid >> 5;
    const int lane = tid & 31;

    const int wsel = blockIdx.x >> 4;            // 0..2
    const int n0   = (blockIdx.x & 15) * BN;     // 16 n-blocks
    const int m0   = blockIdx.y * BM;            // 64 m-blocks

    const __nv_bfloat16* Ag = g_xbf + (size_t)m0 * HID;
    const __nv_bfloat16* Bg = g_wbf + (size_t)wsel * HID * HID + (size_t)n0 * HID;
    const float* WS = (wsel == 0) ? s0 : (wsel == 1 ? s1 : s2);

    if (warp == 0) {
        TCGEN05_ALLOC(sbase + SM_TPTR, 512);
        TCGEN05_RELINQ();
    }
    if (tid == 0) {
        for (int s = 0; s < NK; s++) MBARRIER_INIT(sbase + SM_MBAR + s * 8, 1);
    }
    {
        float* sws = (float*)(dsm + (sbase - smem_u32(dsm)) + SM_WS);
        sws[tid] = WS[n0 + tid];
    }
    __syncthreads();
    uint32_t tmem_base;
    asm volatile("ld.shared.b32 %0, [%1];" : "=r"(tmem_base) : "r"(sbase + SM_TPTR));

    // one stage = A 128 rows x 128B + B 256 rows x 128B, SW128-swizzled
    auto load_stage = [&](int slot, int kt) {
        const int k0 = kt * BKE;                  // bf16 element offset
        const uint32_t abase = sbase + SM_A + slot * A_STG;
        const uint32_t bbase = sbase + SM_B + slot * B_STG;
        const char* ab = (const char*)Ag + (size_t)k0 * 2;
        const char* bb = (const char*)Bg + (size_t)k0 * 2;
        #pragma unroll
        for (int i = 0; i < 4; i++) {             // A: 1024 granules of 16B
            int c = tid + i * 256;
            int row = c >> 3, col = c & 7;
            uint32_t d = abase + (uint32_t)(row * 128 + ((col ^ (row & 7)) << 4));
            const char* p = ab + (size_t)row * (HID * 2) + col * 16;
            asm volatile("cp.async.cg.shared.global [%0], [%1], 16;" :: "r"(d), "l"(p));
        }
        #pragma unroll
        for (int i = 0; i < 8; i++) {             // B: 2048 granules of 16B
            int c = tid + i * 256;
            int row = c >> 3, col = c & 7;
            uint32_t d = bbase + (uint32_t)(row * 128 + ((col ^ (row & 7)) << 4));
            const char* p = bb + (size_t)row * (HID * 2) + col * 16;
            asm volatile("cp.async.cg.shared.global [%0], [%1], 16;" :: "r"(d), "l"(p));
        }
        asm volatile("cp.async.commit_group;" ::: "memory");
    };

    load_stage(0, 0);
    load_stage(1, 1);

    const uint32_t idesc = IDESC_BF16;
    for (int kt = 0; kt < NK; kt++) {
        if (kt + 2 < NK) {
            if (kt >= 2) MBARRIER_WAIT_P0(sbase + SM_MBAR + (kt - 2) * 8);
            load_stage((kt + 2) & (STAGES - 1), kt + 2);
        }
        if (kt + 2 < NK)      asm volatile("cp.async.wait_group 2;" ::: "memory");
        else if (kt + 1 < NK) asm volatile("cp.async.wait_group 1;" ::: "memory");
        else                  asm volatile("cp.async.wait_group 0;" ::: "memory");
        asm volatile("fence.proxy.async.shared::cta;" ::: "memory");
        __syncthreads();

        if (warp == 0) {
            TCGEN05_FENCE_AFTER();
            if (elect_one()) {
                const int slot = kt & (STAGES - 1);
                uint64_t ad = make_desc_sw128(sbase + SM_A + slot * A_STG);
                uint64_t bd = make_desc_sw128(sbase + SM_B + slot * B_STG);
                #pragma unroll
                for (int c = 0; c < 4; c++)       // 4 x K=16 bf16 chunks (32B = +2 units)
                    mma_bf16_ss(tmem_base, ad + c * 2, bd + c * 2, idesc,
                                (kt > 0 || c > 0) ? 1u : 0u);
                TCGEN05_COMMIT(sbase + SM_MBAR + kt * 8);
            }
        }
    }

    MBARRIER_WAIT_P0(sbase + SM_MBAR + (NK - 1) * 8);
    TCGEN05_FENCE_AFTER();

    const int  rsub = (warp & 3) * 32 + lane;     // D row (subpartition-local)
    const int  half = warp >> 2;                  // column half 0/1
    const int  t    = m0 + rsub;
    const float sa  = g_ascale[t];
    float* orow = out + (size_t)wsel * TOK * HID + (size_t)t * HID + n0 + half * 128;
    const float* sws = (const float*)(dsm + (sbase - smem_u32(dsm)) + SM_WS) + half * 128;

    #pragma unroll
    for (int c = 0; c < 4; c++) {
        uint32_t r[32];
        LD_TM_X32(r, tmem_base + half * 128 + c * 32);
        TCGEN05_WAIT_LD();
        #pragma unroll
        for (int j = 0; j < 32; j += 4) {
            float4 v;
            v.x = __uint_as_float(r[j + 0]) * sa * sws[c * 32 + j + 0];
            v.y = __uint_as_float(r[j + 1]) * sa * sws[c * 32 + j + 1];
            v.z = __uint_as_float(r[j + 2]) * sa * sws[c * 32 + j + 2];
            v.w = __uint_as_float(r[j + 3]) * sa * sws[c * 32 + j + 3];
            *(float4*)(orow + c * 32 + j) = v;
        }
    }
    __syncthreads();
    if (warp == 0) TCGEN05_DEALLOC(tmem_base, 512);
#endif  // TC_OK
}

// ---------------------------------------------------------------------------
// Kernel 2b: legacy mma.sync s8 GEMM (active only in the base-arch pass).
// Identical to the round-5 passing kernel.
// ---------------------------------------------------------------------------
__global__ __launch_bounds__(256, 2) void gemm_legacy_kernel(
    const float* __restrict__ s0, const float* __restrict__ s1, const float* __restrict__ s2,
    float* __restrict__ out)
{
#if !TC_OK
    __shared__ int8_t sA[2][LBM * LSROW];
    __shared__ int8_t sB[2][LBN * LSROW];

    const int tid  = threadIdx.x;
    const int bx   = blockIdx.x;
    const int m0   = blockIdx.y * LBM;
    const int wsel = bx >> 5;
    const int n0   = (bx & 31) * LBN;

    const int8_t* W  = g_w + (size_t)wsel * HID * HID;
    const float*  WS = (wsel == 0) ? s0 : (wsel == 1 ? s1 : s2);

    const int8_t* Ag = g_xq + (size_t)m0 * HID;
    const int8_t* Bg = W    + (size_t)n0 * HID;

    const uint32_t sA0 = (uint32_t)__cvta_generic_to_shared(&sA[0][0]);
    const uint32_t sB0 = (uint32_t)__cvta_generic_to_shared(&sB[0][0]);

    auto load_stage = [&](int s, int k0) {
        #pragma unroll
        for (int i = 0; i < 2; i++) {
            int c   = tid + i * 256;
            int row = c >> 2;
            int col = (c & 3) << 4;
            uint32_t da = sA0 + (uint32_t)(s * (LBM * LSROW) + row * LSROW + col);
            const int8_t* pa = Ag + (size_t)row * HID + k0 + col;
            asm volatile("cp.async.cg.shared.global [%0], [%1], 16;\n" :: "r"(da), "l"(pa));
            uint32_t db = sB0 + (uint32_t)(s * (LBN * LSROW) + row * LSROW + col);
            const int8_t* pb = Bg + (size_t)row * HID + k0 + col;
            asm volatile("cp.async.cg.shared.global [%0], [%1], 16;\n" :: "r"(db), "l"(pb));
        }
        asm volatile("cp.async.commit_group;\n" ::: "memory");
    };

    const int warp  = tid >> 5, lane = tid & 31;
    const int wm    = warp >> 1, wn = warp & 1;
    const int mbase = wm * 32,   nbase = wn * 64;
    const int group = lane >> 2, tig = lane & 3;

    int acc[2][8][4];
    #pragma unroll
    for (int im = 0; im < 2; im++)
        #pragma unroll
        for (int jn = 0; jn < 8; jn++)
            #pragma unroll
            for (int q = 0; q < 4; q++) acc[im][jn][q] = 0;

    load_stage(0, 0);

    const int KT = HID / LBK;
    for (int kt = 0; kt < KT; kt++) {
        if (kt + 1 < KT) {
            load_stage((kt + 1) & 1, (kt + 1) * LBK);
            asm volatile("cp.async.wait_group 1;\n" ::: "memory");
        } else {
            asm volatile("cp.async.wait_group 0;\n" ::: "memory");
        }
        __syncthreads();

        const int8_t* a_s = sA[kt & 1];
        const int8_t* b_s = sB[kt & 1];

        #pragma unroll
        for (int kk = 0; kk < 2; kk++) {
            const int ko = kk * 32;
            uint32_t af[2][4], bf[8][2];
            #pragma unroll
            for (int im = 0; im < 2; im++) {
                const int8_t* base = a_s + (mbase + im * 16 + group) * LSROW + ko + tig * 4;
                af[im][0] = *(const uint32_t*)(base);
                af[im][1] = *(const uint32_t*)(base + 8 * LSROW);
                af[im][2] = *(const uint32_t*)(base + 16);
                af[im][3] = *(const uint32_t*)(base + 8 * LSROW + 16);
            }
            #pragma unroll
            for (int jn = 0; jn < 8; jn++) {
                const int8_t* base = b_s + (nbase + jn * 8 + group) * LSROW + ko + tig * 4;
                bf[jn][0] = *(const uint32_t*)(base);
                bf[jn][1] = *(const uint32_t*)(base + 16);
            }
            #pragma unroll
            for (int im = 0; im < 2; im++)
                #pragma unroll
                for (int jn = 0; jn < 8; jn++)
                    asm volatile(
                        "mma.sync.aligned.m16n8k32.row.col.s32.s8.s8.s32 "
                        "{%0,%1,%2,%3},{%4,%5,%6,%7},{%8,%9},{%0,%1,%2,%3};\n"
                        : "+r"(acc[im][jn][0]), "+r"(acc[im][jn][1]),
                          "+r"(acc[im][jn][2]), "+r"(acc[im][jn][3])
                        : "r"(af[im][0]), "r"(af[im][1]), "r"(af[im][2]), "r"(af[im][3]),
                          "r"(bf[jn][0]), "r"(bf[jn][1]));
        }
        __syncthreads();
    }

    float* obase = out + (size_t)wsel * TOK * HID;
    #pragma unroll
    for (int im = 0; im < 2; im++) {
        const int t   = m0 + mbase + im * 16 + group;
        const float sa0 = g_ascale[t];
        const float sa1 = g_ascale[t + 8];
        #pragma unroll
        for (int jn = 0; jn < 8; jn++) {
            const int nl = n0 + nbase + jn * 8 + tig * 2;
            const float ws0 = WS[nl], ws1 = WS[nl + 1];
            float2 v0, v1;
            v0.x = (float)acc[im][jn][0] * sa0 * ws0;
            v0.y = (float)acc[im][jn][1] * sa0 * ws1;
            v1.x = (float)acc[im][jn][2] * sa1 * ws0;
            v1.y = (float)acc[im][jn][3] * sa1 * ws1;
            *(float2*)(obase + (size_t)t * HID + nl)       = v0;
            *(float2*)(obase + (size_t)(t + 8) * HID + nl) = v1;
        }
    }
#endif  // !TC_OK
}

// ---------------------------------------------------------------------------
extern "C" void kernel_launch(void* const* d_in, const int* in_sizes, int n_in,
                              void* d_out, int out_size)
{
    const float* hs = (const float*)d_in[0];
    const float* lt = (const float*)d_in[1];
    const float* rt = (const float*)d_in[2];
    const void*  wq = d_in[3];
    const float* sq = (const float*)d_in[4];
    const void*  wk = d_in[5];
    const float* sk = (const float*)d_in[6];
    const void*  wv = d_in[7];
    const float* sv = (const float*)d_in[8];
    float* out = (float*)d_out;

    detect_dtype_kernel<<<1, 32>>>((const unsigned int*)wq);

    dim3 cgrid((HID * HID) / 4 / 256, 3);
    convert_weights_kernel<<<cgrid, 256>>>(wq, wk, wv);

    transform_quant_kernel<<<TOK, 256>>>(hs, lt, rt);

    // tcgen05 path (no-op body if only the base-arch SASS was built)
    cudaFuncSetAttribute(gemm_tc_kernel,
                         cudaFuncAttributeMaxDynamicSharedMemorySize, SMEM_DYN);
    dim3 tgrid(48, 64);
    gemm_tc_kernel<<<tgrid, 256, SMEM_DYN>>>(sq, sk, sv, out);

    // legacy path (no-op body in the sm_103a SASS)
    dim3 lgrid(96, 64);
    gemm_legacy_kernel<<<lgrid, 256>>>(sq, sk, sv, out);
}